// round 15
// baseline (speedup 1.0000x reference)
#include <cuda_runtime.h>
#include <cuda_bf16.h>
#include <cstdint>

#define NN 100000
#define NEDGE 3200000
#define CIN 768
#define C 64
#define NOUT 192
#define NB1 98  /* ceil(100000/1024) */

// ---------------- static device scratch ----------------
__device__ __align__(16) __nv_bfloat16 g_xlb[(size_t)NN * C];  // bf16 x_l for edge phase
__device__ float g_xr[(size_t)NN * C];
__device__ __align__(16) __nv_bfloat16 g_bhi[768 * NOUT];  // [k][n], rows of 384B
__device__ __align__(16) __nv_bfloat16 g_blo[768 * NOUT];
__device__ int   g_deg[NN];
__device__ int   g_tmp[NN];
__device__ int   g_bsum[128];
__device__ int   g_boff[128];
__device__ int   g_rowptr[NN + 1];
__device__ int   g_cursor[NN];
__device__ int   g_csrc[NEDGE];

// ---------------- smem layout (bytes): A double-buffered, B half-stage ring ----
#define SA_STRIDE 144          /* 72 bf16 per row (64 + 8 pad) */
#define SB_STRIDE 400          /* 200 bf16 per row (192 + 8 pad) */
#define OFF_A0H  0             /* 64 x 144 = 9216 */
#define OFF_A0L  9216
#define OFF_A1H  18432
#define OFF_A1L  27648
#define OFF_BH   36864         /* 64 x 400 = 25600 (2 stages of 32 rows) */
#define OFF_BL   62464
#define OFF_BIAS 88064         /* 192 floats */
#define SMEM_TOT 88832

__device__ __forceinline__ uint32_t smem_u32(const void* p) {
    uint32_t a;
    asm("{ .reg .u64 t; cvta.to.shared.u64 t, %1; cvt.u32.u64 %0, t; }"
        : "=r"(a) : "l"(p));
    return a;
}
__device__ __forceinline__ void cpa16(uint32_t dst, const void* src) {
    asm volatile("cp.async.cg.shared.global [%0], [%1], 16;"
                 :: "r"(dst), "l"(src) : "memory");
}
#define CPA_COMMIT() asm volatile("cp.async.commit_group;" ::: "memory")
#define CPA_WAIT1()  asm volatile("cp.async.wait_group 1;" ::: "memory")
__device__ __forceinline__ void ldsm4(uint32_t* r, uint32_t addr) {
    asm volatile("ldmatrix.sync.aligned.m8n8.x4.shared.b16 {%0,%1,%2,%3}, [%4];"
                 : "=r"(r[0]), "=r"(r[1]), "=r"(r[2]), "=r"(r[3]) : "r"(addr));
}
__device__ __forceinline__ void ldsm4t(uint32_t* r, uint32_t addr) {
    asm volatile("ldmatrix.sync.aligned.m8n8.x4.trans.shared.b16 {%0,%1,%2,%3}, [%4];"
                 : "=r"(r[0]), "=r"(r[1]), "=r"(r[2]), "=r"(r[3]) : "r"(addr));
}
__device__ __forceinline__ void mma16816(float* d, const uint32_t* a,
                                         uint32_t b0, uint32_t b1) {
    asm volatile(
        "mma.sync.aligned.m16n8k16.row.col.f32.bf16.bf16.f32 "
        "{%0,%1,%2,%3}, {%4,%5,%6,%7}, {%8,%9}, {%0,%1,%2,%3};"
        : "+f"(d[0]), "+f"(d[1]), "+f"(d[2]), "+f"(d[3])
        : "r"(a[0]), "r"(a[1]), "r"(a[2]), "r"(a[3]), "r"(b0), "r"(b1));
}

// ---- packed f32x2 helpers (fma.rn.f32x2 proven on this toolchain in R3) ----
__device__ __forceinline__ unsigned long long pk2(float lo, float hi) {
    unsigned long long r;
    asm("mov.b64 %0, {%1, %2};" : "=l"(r) : "f"(lo), "f"(hi));
    return r;
}
__device__ __forceinline__ unsigned long long bc2(float x) {
    unsigned long long r;
    asm("mov.b64 %0, {%1, %1};" : "=l"(r) : "f"(x));
    return r;
}
__device__ __forceinline__ float2 up2(unsigned long long v) {
    float2 r;
    asm("mov.b64 {%0, %1}, %2;" : "=f"(r.x), "=f"(r.y) : "l"(v));
    return r;
}
__device__ __forceinline__ unsigned long long ffma2(unsigned long long a,
                                                    unsigned long long b,
                                                    unsigned long long c) {
    unsigned long long d;
    asm("fma.rn.f32x2 %0, %1, %2, %3;" : "=l"(d) : "l"(a), "l"(b), "l"(c));
    return d;
}
__device__ __forceinline__ unsigned long long abs2(unsigned long long t) {
    unsigned long long d;
    asm("and.b64 %0, %1, 0x7FFFFFFF7FFFFFFF;" : "=l"(d) : "l"(t));
    return d;
}

// ---------------- W prep: split into bf16 hi/lo, [k][n] layout ----------------
__global__ void k_wprep(const float* __restrict__ Wl, const float* __restrict__ Wr,
                        const float* __restrict__ Wn) {
    const int i = blockIdx.x * 256 + threadIdx.x;
    if (i >= 768 * NOUT) return;
    const int k = i / NOUT, n = i % NOUT;
    const float* W = n < 64 ? Wl : n < 128 ? Wr : Wn;
    const float w = W[k * 64 + (n & 63)];
    const __nv_bfloat16 h = __float2bfloat16(w);
    g_bhi[i] = h;
    g_blo[i] = __float2bfloat16(w - __bfloat162float(h));
}

// ---------------- tensor-core triple GEMM: 64x192 tile, pipelined (FROZEN) ----
__global__ void __launch_bounds__(256, 2)
k_gemm_mma(const float* __restrict__ node,
           const float* __restrict__ bl, const float* __restrict__ br,
           const float* __restrict__ bn, const float* __restrict__ gb,
           float* __restrict__ out) {
    extern __shared__ char smem[];
    const uint32_t sb = smem_u32(smem);
    const int tid = threadIdx.x;
    const int warp = tid >> 5, lane = tid & 31;
    const int r0 = blockIdx.x * 64;

    if (tid < NOUT) {
        const float b = tid < 64 ? bl[tid]
                      : tid < 128 ? br[tid - 64]
                      : bn[tid - 128] + gb[tid - 128];
        *(float*)(smem + OFF_BIAS + tid * 4) = b;
    }

    float acc[2][6][4];
#pragma unroll
    for (int mi = 0; mi < 2; mi++)
#pragma unroll
        for (int ni = 0; ni < 6; ni++)
#pragma unroll
            for (int j = 0; j < 4; j++) acc[mi][ni][j] = 0.f;

    const int wm = warp & 1, wn = warp >> 1;
    const int m_base = wm * 32;
    const int n_base = wn * 48;
    const int a_row = lane & 15;
    const int a_koff = (lane >> 4) << 3;
    const int b_row = lane & 15;
    const int b_noff = (lane >> 4) << 3;

    const int ar = tid >> 4;
    const int ac4 = tid & 15;

    auto fill_stage = [&](int s, int kcn) {
#pragma unroll
        for (int i = 0; i < 3; i++) {
            const int q = tid + i * 256;
            const int rr = q / 24, f = q % 24;
            const uint32_t off = (uint32_t)((s * 32 + rr) * SB_STRIDE + f * 16);
            const size_t srow = (size_t)(kcn * 64 + s * 32 + rr) * 384 + f * 16;
            cpa16(sb + OFF_BH + off, (const char*)g_bhi + srow);
            cpa16(sb + OFF_BL + off, (const char*)g_blo + srow);
        }
    };
    float4 areg[4];
    auto lda = [&](int kcn) {
#pragma unroll
        for (int i = 0; i < 4; i++) {
            const int r = ar + i * 16;
            areg[i] = (r0 + r < NN)
                ? *(const float4*)(node + (size_t)(r0 + r) * CIN + kcn * 64 + ac4 * 4)
                : make_float4(0.f, 0.f, 0.f, 0.f);
        }
    };
    auto cvta = [&](int p) {
        const int offh = p ? OFF_A1H : OFF_A0H;
        const int offl = p ? OFF_A1L : OFF_A0L;
#pragma unroll
        for (int i = 0; i < 4; i++) {
            const int r = ar + i * 16;
            const float4 v = areg[i];
            const __nv_bfloat16 h0 = __float2bfloat16(v.x), h1 = __float2bfloat16(v.y);
            const __nv_bfloat16 h2 = __float2bfloat16(v.z), h3 = __float2bfloat16(v.w);
            __nv_bfloat162* ph = (__nv_bfloat162*)(smem + offh + r * SA_STRIDE + ac4 * 8);
            ph[0] = __nv_bfloat162(h0, h1);
            ph[1] = __nv_bfloat162(h2, h3);
            const __nv_bfloat16 l0 = __float2bfloat16(v.x - __bfloat162float(h0));
            const __nv_bfloat16 l1 = __float2bfloat16(v.y - __bfloat162float(h1));
            const __nv_bfloat16 l2 = __float2bfloat16(v.z - __bfloat162float(h2));
            const __nv_bfloat16 l3 = __float2bfloat16(v.w - __bfloat162float(h3));
            __nv_bfloat162* pl = (__nv_bfloat162*)(smem + offl + r * SA_STRIDE + ac4 * 8);
            pl[0] = __nv_bfloat162(l0, l1);
            pl[1] = __nv_bfloat162(l2, l3);
        }
    };
    auto mma_half = [&](int half, int p) {
        const int offh = p ? OFF_A1H : OFF_A0H;
        const int offl = p ? OFF_A1L : OFF_A0L;
#pragma unroll
        for (int ks = half * 2; ks < half * 2 + 2; ks++) {
            const int k0 = ks * 16;
            uint32_t ah[2][4], al[2][4];
#pragma unroll
            for (int mi = 0; mi < 2; mi++) {
                const uint32_t aoff =
                    (uint32_t)((m_base + 16 * mi + a_row) * SA_STRIDE + (k0 + a_koff) * 2);
                ldsm4(ah[mi], sb + offh + aoff);
                ldsm4(al[mi], sb + offl + aoff);
            }
#pragma unroll
            for (int np = 0; np < 3; np++) {
                const int n0 = n_base + np * 16;
                const uint32_t boff =
                    (uint32_t)((k0 + b_row) * SB_STRIDE + (n0 + b_noff) * 2);
                uint32_t bh[4];
                ldsm4t(bh, sb + OFF_BH + boff);
#pragma unroll
                for (int mi = 0; mi < 2; mi++) {
                    mma16816(acc[mi][2 * np],     ah[mi], bh[0], bh[1]);
                    mma16816(acc[mi][2 * np + 1], ah[mi], bh[2], bh[3]);
                    mma16816(acc[mi][2 * np],     al[mi], bh[0], bh[1]);
                    mma16816(acc[mi][2 * np + 1], al[mi], bh[2], bh[3]);
                }
                uint32_t bo[4];
                ldsm4t(bo, sb + OFF_BL + boff);
#pragma unroll
                for (int mi = 0; mi < 2; mi++) {
                    mma16816(acc[mi][2 * np],     ah[mi], bo[0], bo[1]);
                    mma16816(acc[mi][2 * np + 1], ah[mi], bo[2], bo[3]);
                }
            }
        }
    };

    lda(0);
    fill_stage(0, 0); CPA_COMMIT();
    fill_stage(1, 0); CPA_COMMIT();
    cvta(0);
    int p = 0;

    for (int kc = 0; kc < 12; kc++) {
        const int kcn = (kc < 11) ? kc + 1 : 11;
        CPA_WAIT1(); __syncthreads();
        lda(kcn);
        mma_half(0, p);
        __syncthreads();
        fill_stage(0, kcn); CPA_COMMIT();
        CPA_WAIT1(); __syncthreads();
        mma_half(1, p);
        cvta(p ^ 1);
        __syncthreads();
        fill_stage(1, kcn); CPA_COMMIT();
        p ^= 1;
    }

    // epilogue: x_l -> bf16 g_xlb; x_r -> fp32 g_xr; lin -> out
    const int g2 = lane >> 2;
    const int i2 = (lane & 3) << 1;
    const float* bias = (const float*)(smem + OFF_BIAS);
#pragma unroll
    for (int mi = 0; mi < 2; mi++) {
        const int r1 = r0 + m_base + 16 * mi + g2;
#pragma unroll
        for (int ni = 0; ni < 6; ni++) {
            const int n = n_base + 8 * ni + i2;
            const float b0 = bias[n], b1 = bias[n + 1];
            const float v00 = acc[mi][ni][0] + b0, v01 = acc[mi][ni][1] + b1;
            const float v10 = acc[mi][ni][2] + b0, v11 = acc[mi][ni][3] + b1;
            if (n < 64) {
                if (r1 < NN)
                    *(__nv_bfloat162*)(g_xlb + (size_t)r1 * C + n) =
                        __float22bfloat162_rn(make_float2(v00, v01));
                if (r1 + 8 < NN)
                    *(__nv_bfloat162*)(g_xlb + (size_t)(r1 + 8) * C + n) =
                        __float22bfloat162_rn(make_float2(v10, v11));
            } else {
                float* basep;
                int col;
                if (n < 128) { basep = g_xr; col = n - 64; }
                else         { basep = out;  col = n - 128; }
                if (r1 < NN)
                    *(float2*)(basep + (size_t)r1 * C + col) = make_float2(v00, v01);
                if (r1 + 8 < NN)
                    *(float2*)(basep + (size_t)(r1 + 8) * C + col) = make_float2(v10, v11);
            }
        }
    }
}

// ---------------- CSR build ----------------
__global__ void k_zero() {
    int i = blockIdx.x * 256 + threadIdx.x;
    if (i < NN) g_deg[i] = 0;
}
__global__ void k_hist(const int* __restrict__ ei) {
    int e = blockIdx.x * 256 + threadIdx.x;
    if (e < NEDGE) atomicAdd(&g_deg[ei[NEDGE + e]], 1);
}
__global__ void k_scan1() {
    __shared__ int s[1024];
    const int gid = blockIdx.x * 1024 + threadIdx.x;
    int v = (gid < NN) ? g_deg[gid] : 0;
    s[threadIdx.x] = v;
    __syncthreads();
#pragma unroll
    for (int off = 1; off < 1024; off <<= 1) {
        int t = (threadIdx.x >= off) ? s[threadIdx.x - off] : 0;
        __syncthreads();
        s[threadIdx.x] += t;
        __syncthreads();
    }
    if (gid < NN) g_tmp[gid] = s[threadIdx.x];
    if (threadIdx.x == 1023) g_bsum[blockIdx.x] = s[1023];
}
__global__ void k_scan2() {
    __shared__ int s[128];
    const int t = threadIdx.x;
    int v = (t < NB1) ? g_bsum[t] : 0;
    s[t] = v;
    __syncthreads();
#pragma unroll
    for (int off = 1; off < 128; off <<= 1) {
        int u = (t >= off) ? s[t - off] : 0;
        __syncthreads();
        s[t] += u;
        __syncthreads();
    }
    g_boff[t] = s[t] - v;
}
__global__ void k_scan3() {
    const int i = blockIdx.x * 256 + threadIdx.x;
    if (i < NN) {
        int rp = g_tmp[i] - g_deg[i] + g_boff[i >> 10];
        g_rowptr[i] = rp;
        g_cursor[i] = rp;
    }
    if (i == 0) g_rowptr[NN] = NEDGE;
}
__global__ void k_scatter(const int* __restrict__ ei) {
    int e = blockIdx.x * 256 + threadIdx.x;
    if (e < NEDGE) {
        int src = ei[e];
        int dst = ei[NEDGE + e];
        int pos = atomicAdd(&g_cursor[dst], 1);
        g_csrc[pos] = src;
    }
}

// ---------------- fused edge phase: sector-packed gathers + f32x2 packed math ----
// Lane s loads uint4 idx {s, 4+s}: the 4-lane group covers 64B contiguously per
// LDG (full sectors). Channels owned by lane s: [8s,8s+8) and [32+8s,32+8s+8).
// lrelu(t) = 0.6t + 0.4|t| (exact identity for max(t, 0.2t)) in fma.rn.f32x2.
__global__ void __launch_bounds__(256)
k_fused(const float* __restrict__ att, float* __restrict__ out) {
    const int w = (blockIdx.x * 256 + threadIdx.x) >> 5;
    if (w >= NN) return;
    const int lane = threadIdx.x & 31;
    const int g = lane >> 2;          // edge group 0..7
    const int s = lane & 3;
    const int dst = w;

    const float2* attf2 = (const float2*)att;
    const float2* xrf2  = (const float2*)g_xr + (size_t)dst * 32;
    const uint4*  xlb4  = (const uint4*)g_xlb;   // row = 8 uint4

    const unsigned long long ONE2 = bc2(1.0f);
    const unsigned long long C06  = bc2(0.6f);
    const unsigned long long C04  = bc2(0.4f);

    unsigned long long a2[8], xr2[8];
#pragma unroll
    for (int k = 0; k < 4; k++) {
        float2 t;
        t = attf2[4 * s + k];       a2[k]     = pk2(t.x, t.y);
        t = attf2[16 + 4 * s + k];  a2[4 + k] = pk2(t.x, t.y);
        t = xrf2[4 * s + k];        xr2[k]     = pk2(t.x, t.y);
        t = xrf2[16 + 4 * s + k];   xr2[4 + k] = pk2(t.x, t.y);
    }

    const int start = g_rowptr[dst];
    const int total = g_rowptr[dst + 1] - start + 1;  // + self loop at virtual idx 0
    const int deg = total - 1;

    const int p0 = (lane < deg)      ? g_csrc[start + lane]      : 0;
    const int p1 = (lane + 32 < deg) ? g_csrc[start + 32 + lane] : 0;

    unsigned long long acc2[8];
#pragma unroll
    for (int k = 0; k < 8; k++) acc2[k] = 0ull;
    float d = 0.f;

    for (int base = 0; base < total; base += 8) {
        const int idx = base + g;
        const bool valid = idx < total;
        const int sh0 = __shfl_sync(0xffffffffu, p0, (idx - 1) & 31);
        const int sh1 = __shfl_sync(0xffffffffu, p1, (idx - 33) & 31);
        unsigned long long x2[8];
#pragma unroll
        for (int k = 0; k < 8; k++) x2[k] = 0ull;
        float ek = 0.f;
        if (valid) {
            int src;
            if (idx == 0)       src = dst;
            else if (idx <= 32) src = sh0;
            else if (idx <= 64) src = sh1;
            else                src = g_csrc[start + idx - 1];  // ~never taken
            const uint4 u0 = xlb4[(size_t)src * 8 + s];       // channels 8s..8s+7
            const uint4 u1 = xlb4[(size_t)src * 8 + 4 + s];   // channels 32+8s..+7
            {
                float2 f;
                f = __bfloat1622float2(*(const __nv_bfloat162*)&u0.x); x2[0] = pk2(f.x, f.y);
                f = __bfloat1622float2(*(const __nv_bfloat162*)&u0.y); x2[1] = pk2(f.x, f.y);
                f = __bfloat1622float2(*(const __nv_bfloat162*)&u0.z); x2[2] = pk2(f.x, f.y);
                f = __bfloat1622float2(*(const __nv_bfloat162*)&u0.w); x2[3] = pk2(f.x, f.y);
                f = __bfloat1622float2(*(const __nv_bfloat162*)&u1.x); x2[4] = pk2(f.x, f.y);
                f = __bfloat1622float2(*(const __nv_bfloat162*)&u1.y); x2[5] = pk2(f.x, f.y);
                f = __bfloat1622float2(*(const __nv_bfloat162*)&u1.z); x2[6] = pk2(f.x, f.y);
                f = __bfloat1622float2(*(const __nv_bfloat162*)&u1.w); x2[7] = pk2(f.x, f.y);
            }
            unsigned long long ek2 = 0ull;
#pragma unroll
            for (int k = 0; k < 8; k++) {
                const unsigned long long t  = ffma2(x2[k], ONE2, xr2[k]);
                const unsigned long long lr = ffma2(t, C06, ffma2(abs2(t), C04, 0ull));
                ek2 = ffma2(a2[k], lr, ek2);
            }
            const float2 ef = up2(ek2);
            ek = ef.x + ef.y;
        }
        ek += __shfl_xor_sync(0xffffffffu, ek, 1);
        ek += __shfl_xor_sync(0xffffffffu, ek, 2);
        const float p = valid ? __expf(ek) : 0.f;
        d += p;
        const unsigned long long p2 = bc2(p);
#pragma unroll
        for (int k = 0; k < 8; k++)
            acc2[k] = ffma2(p2, x2[k], acc2[k]);
    }

    // cross-group reduction (groups differ in lane bits 2-4)
#pragma unroll
    for (int o = 4; o <= 16; o <<= 1) {
        d += __shfl_xor_sync(0xffffffffu, d, o);
#pragma unroll
        for (int k = 0; k < 8; k++) {
            const unsigned long long other = __shfl_xor_sync(0xffffffffu, acc2[k], o);
            acc2[k] = ffma2(other, ONE2, acc2[k]);
        }
    }

    if (g == 0) {
        const float inv = 1.0f / d;
        float2* o2 = (float2*)out + (size_t)dst * 32;
#pragma unroll
        for (int k = 0; k < 8; k++) {
            const int f2i = (k < 4) ? (4 * s + k) : (16 + 4 * s + (k - 4));
            const float2 av = up2(acc2[k]);
            float2 l = o2[f2i];
            l.x = fmaxf(l.x + av.x * inv, 0.f);
            l.y = fmaxf(l.y + av.y * inv, 0.f);
            o2[f2i] = l;
        }
    }
}

// ---------------- launch: GEMM (stream 0) overlapped with CSR build (s2) ----------------
extern "C" void kernel_launch(void* const* d_in, const int* in_sizes, int n_in,
                              void* d_out, int out_size) {
    const float* node = (const float*)d_in[0];
    const int*   ei   = (const int*)d_in[1];   // int32 on device
    const float* Wl   = (const float*)d_in[2];
    const float* bl   = (const float*)d_in[3];
    const float* Wr   = (const float*)d_in[4];
    const float* br   = (const float*)d_in[5];
    const float* att  = (const float*)d_in[6];
    const float* gb   = (const float*)d_in[7];
    const float* Wn   = (const float*)d_in[8];
    const float* bn   = (const float*)d_in[9];
    float* out = (float*)d_out;

    static cudaStream_t s2 = nullptr;
    static cudaEvent_t ev_fork = nullptr, ev_join = nullptr;
    if (!s2) {  // first call happens outside graph capture
        cudaStreamCreateWithFlags(&s2, cudaStreamNonBlocking);
        cudaEventCreateWithFlags(&ev_fork, cudaEventDisableTiming);
        cudaEventCreateWithFlags(&ev_join, cudaEventDisableTiming);
        cudaFuncSetAttribute(k_gemm_mma, cudaFuncAttributeMaxDynamicSharedMemorySize, SMEM_TOT);
    }

    cudaEventRecord(ev_fork, 0);
    cudaStreamWaitEvent(s2, ev_fork, 0);
    k_zero<<<(NN + 255) / 256, 256, 0, s2>>>();              // launch 1
    k_hist<<<(NEDGE + 255) / 256, 256, 0, s2>>>(ei);         // launch 2
    k_wprep<<<(768 * NOUT + 255) / 256, 256>>>(Wl, Wr, Wn);  // launch 3
    k_gemm_mma<<<(NN + 63) / 64, 256, SMEM_TOT>>>(node, bl, br, bn, gb, out);  // launch 4 (profiled)
    k_scan1<<<NB1, 1024, 0, s2>>>();
    k_scan2<<<1, 128, 0, s2>>>();
    k_scan3<<<(NN + 255) / 256, 256, 0, s2>>>();
    k_scatter<<<(NEDGE + 255) / 256, 256, 0, s2>>>(ei);
    cudaEventRecord(ev_join, s2);

    cudaStreamWaitEvent(0, ev_join, 0);
    k_fused<<<(NN * 32 + 255) / 256, 256>>>(att, out);
}

// round 16
// speedup vs baseline: 1.0315x; 1.0315x over previous
#include <cuda_runtime.h>
#include <cuda_bf16.h>
#include <cstdint>

#define NN 100000
#define NEDGE 3200000
#define CIN 768
#define C 64
#define NOUT 192
#define NB1 98  /* ceil(100000/1024) */

// ---------------- static device scratch ----------------
__device__ __align__(16) __nv_bfloat16 g_xlb[(size_t)NN * C];  // bf16 x_l for edge phase
__device__ float g_xr[(size_t)NN * C];
__device__ __align__(16) __nv_bfloat16 g_bhi[768 * NOUT];  // [k][n], rows of 384B
__device__ __align__(16) __nv_bfloat16 g_blo[768 * NOUT];
__device__ int   g_deg[NN];
__device__ int   g_tmp[NN];
__device__ int   g_bsum[128];
__device__ int   g_boff[128];
__device__ int   g_rowptr[NN + 1];
__device__ int   g_cursor[NN];
__device__ int   g_csrc[NEDGE];

// ---------------- smem layout (bytes): 64x96 tile, A dbl-buffered, B half-stage ring
#define SA_STRIDE 144          /* 72 bf16 per row (64 + 8 pad) */
#define SB_STRIDE 208          /* 104 bf16 per row (96 + 8 pad) */
#define OFF_A0H  0             /* 64 x 144 = 9216 */
#define OFF_A0L  9216
#define OFF_A1H  18432
#define OFF_A1L  27648
#define OFF_BH   36864         /* 64 x 208 = 13312 (2 stages of 32 rows) */
#define OFF_BL   50176
#define OFF_BIAS 63488         /* 192 floats */
#define SMEM_TOT 64256

__device__ __forceinline__ uint32_t smem_u32(const void* p) {
    uint32_t a;
    asm("{ .reg .u64 t; cvta.to.shared.u64 t, %1; cvt.u32.u64 %0, t; }"
        : "=r"(a) : "l"(p));
    return a;
}
__device__ __forceinline__ void cpa16(uint32_t dst, const void* src) {
    asm volatile("cp.async.cg.shared.global [%0], [%1], 16;"
                 :: "r"(dst), "l"(src) : "memory");
}
#define CPA_COMMIT() asm volatile("cp.async.commit_group;" ::: "memory")
#define CPA_WAIT1()  asm volatile("cp.async.wait_group 1;" ::: "memory")
__device__ __forceinline__ void ldsm4(uint32_t* r, uint32_t addr) {
    asm volatile("ldmatrix.sync.aligned.m8n8.x4.shared.b16 {%0,%1,%2,%3}, [%4];"
                 : "=r"(r[0]), "=r"(r[1]), "=r"(r[2]), "=r"(r[3]) : "r"(addr));
}
__device__ __forceinline__ void ldsm4t(uint32_t* r, uint32_t addr) {
    asm volatile("ldmatrix.sync.aligned.m8n8.x4.trans.shared.b16 {%0,%1,%2,%3}, [%4];"
                 : "=r"(r[0]), "=r"(r[1]), "=r"(r[2]), "=r"(r[3]) : "r"(addr));
}
__device__ __forceinline__ void mma16816(float* d, const uint32_t* a,
                                         uint32_t b0, uint32_t b1) {
    asm volatile(
        "mma.sync.aligned.m16n8k16.row.col.f32.bf16.bf16.f32 "
        "{%0,%1,%2,%3}, {%4,%5,%6,%7}, {%8,%9}, {%0,%1,%2,%3};"
        : "+f"(d[0]), "+f"(d[1]), "+f"(d[2]), "+f"(d[3])
        : "r"(a[0]), "r"(a[1]), "r"(a[2]), "r"(a[3]), "r"(b0), "r"(b1));
}

// ---------------- W prep: split into bf16 hi/lo, [k][n] layout ----------------
__global__ void k_wprep(const float* __restrict__ Wl, const float* __restrict__ Wr,
                        const float* __restrict__ Wn) {
    const int i = blockIdx.x * 256 + threadIdx.x;
    if (i >= 768 * NOUT) return;
    const int k = i / NOUT, n = i % NOUT;
    const float* W = n < 64 ? Wl : n < 128 ? Wr : Wn;
    const float w = W[k * 64 + (n & 63)];
    const __nv_bfloat16 h = __float2bfloat16(w);
    g_bhi[i] = h;
    g_blo[i] = __float2bfloat16(w - __bfloat162float(h));
}

// ---------------- tensor-core triple GEMM: 64x96 tile, 3 CTAs/SM ----------------
__global__ void __launch_bounds__(256, 3)
k_gemm_mma(const float* __restrict__ node,
           const float* __restrict__ bl, const float* __restrict__ br,
           const float* __restrict__ bn, const float* __restrict__ gb,
           float* __restrict__ out) {
    extern __shared__ char smem[];
    const uint32_t sb = smem_u32(smem);
    const int tid = threadIdx.x;
    const int warp = tid >> 5, lane = tid & 31;
    const int r0 = (blockIdx.x >> 1) * 64;
    const int nh = blockIdx.x & 1;          // N-half: cols nh*96 .. nh*96+95

    if (tid < NOUT) {
        const float b = tid < 64 ? bl[tid]
                      : tid < 128 ? br[tid - 64]
                      : bn[tid - 128] + gb[tid - 128];
        *(float*)(smem + OFF_BIAS + tid * 4) = b;
    }

    float acc[6][4];
#pragma unroll
    for (int ni = 0; ni < 6; ni++)
#pragma unroll
        for (int j = 0; j < 4; j++) acc[ni][j] = 0.f;

    const int wm = warp & 3, wn = warp >> 2;   // 4 x 2 warp grid
    const int m_base = wm * 16;                // warp tile 16 x 48
    const int n_base = wn * 48;
    const int a_row = lane & 15;
    const int a_koff = (lane >> 4) << 3;
    const int b_row = lane & 15;
    const int b_noff = (lane >> 4) << 3;

    const int ar = tid >> 4;            // A-load base row (0..15)
    const int ac4 = tid & 15;           // float4 column

    auto fill_stage = [&](int s, int kcn) {
#pragma unroll
        for (int i = 0; i < 2; i++) {
            const int q = tid + i * 256;          // 0..511, use 0..383
            if (q < 384) {
                const int rr = q / 12, f = q % 12;   // 12 x 16B = 192B half-row
                const uint32_t off = (uint32_t)((s * 32 + rr) * SB_STRIDE + f * 16);
                const size_t srow = (size_t)(kcn * 64 + s * 32 + rr) * 384 + nh * 192 + f * 16;
                cpa16(sb + OFF_BH + off, (const char*)g_bhi + srow);
                cpa16(sb + OFF_BL + off, (const char*)g_blo + srow);
            }
        }
    };
    float4 areg[4];
    auto lda = [&](int kcn) {
#pragma unroll
        for (int i = 0; i < 4; i++) {
            const int r = ar + i * 16;
            areg[i] = (r0 + r < NN)
                ? *(const float4*)(node + (size_t)(r0 + r) * CIN + kcn * 64 + ac4 * 4)
                : make_float4(0.f, 0.f, 0.f, 0.f);
        }
    };
    auto cvta = [&](int p) {
        const int offh = p ? OFF_A1H : OFF_A0H;
        const int offl = p ? OFF_A1L : OFF_A0L;
#pragma unroll
        for (int i = 0; i < 4; i++) {
            const int r = ar + i * 16;
            const float4 v = areg[i];
            const __nv_bfloat16 h0 = __float2bfloat16(v.x), h1 = __float2bfloat16(v.y);
            const __nv_bfloat16 h2 = __float2bfloat16(v.z), h3 = __float2bfloat16(v.w);
            __nv_bfloat162* ph = (__nv_bfloat162*)(smem + offh + r * SA_STRIDE + ac4 * 8);
            ph[0] = __nv_bfloat162(h0, h1);
            ph[1] = __nv_bfloat162(h2, h3);
            const __nv_bfloat16 l0 = __float2bfloat16(v.x - __bfloat162float(h0));
            const __nv_bfloat16 l1 = __float2bfloat16(v.y - __bfloat162float(h1));
            const __nv_bfloat16 l2 = __float2bfloat16(v.z - __bfloat162float(h2));
            const __nv_bfloat16 l3 = __float2bfloat16(v.w - __bfloat162float(h3));
            __nv_bfloat162* pl = (__nv_bfloat162*)(smem + offl + r * SA_STRIDE + ac4 * 8);
            pl[0] = __nv_bfloat162(l0, l1);
            pl[1] = __nv_bfloat162(l2, l3);
        }
    };
    auto mma_half = [&](int half, int p) {
        const int offh = p ? OFF_A1H : OFF_A0H;
        const int offl = p ? OFF_A1L : OFF_A0L;
#pragma unroll
        for (int ks = half * 2; ks < half * 2 + 2; ks++) {
            const int k0 = ks * 16;
            uint32_t ah[4], al[4];
            const uint32_t aoff =
                (uint32_t)((m_base + a_row) * SA_STRIDE + (k0 + a_koff) * 2);
            ldsm4(ah, sb + offh + aoff);
            ldsm4(al, sb + offl + aoff);
#pragma unroll
            for (int np = 0; np < 3; np++) {
                const int n0 = n_base + np * 16;
                const uint32_t boff =
                    (uint32_t)((k0 + b_row) * SB_STRIDE + (n0 + b_noff) * 2);
                uint32_t bh[4];
                ldsm4t(bh, sb + OFF_BH + boff);
                mma16816(acc[2 * np],     ah, bh[0], bh[1]);
                mma16816(acc[2 * np + 1], ah, bh[2], bh[3]);
                mma16816(acc[2 * np],     al, bh[0], bh[1]);
                mma16816(acc[2 * np + 1], al, bh[2], bh[3]);
                uint32_t bo[4];
                ldsm4t(bo, sb + OFF_BL + boff);
                mma16816(acc[2 * np],     ah, bo[0], bo[1]);
                mma16816(acc[2 * np + 1], ah, bo[2], bo[3]);
            }
        }
    };

    lda(0);
    fill_stage(0, 0); CPA_COMMIT();
    fill_stage(1, 0); CPA_COMMIT();
    cvta(0);
    int p = 0;

    for (int kc = 0; kc < 12; kc++) {
        const int kcn = (kc < 11) ? kc + 1 : 11;
        CPA_WAIT1(); __syncthreads();
        lda(kcn);
        mma_half(0, p);
        __syncthreads();
        fill_stage(0, kcn); CPA_COMMIT();
        CPA_WAIT1(); __syncthreads();
        mma_half(1, p);
        cvta(p ^ 1);
        __syncthreads();
        fill_stage(1, kcn); CPA_COMMIT();
        p ^= 1;
    }

    // epilogue: route global col n: [0,64)->g_xlb (bf16), [64,128)->g_xr, [128,192)->out
    const int g2 = lane >> 2;
    const int i2 = (lane & 3) << 1;
    const float* bias = (const float*)(smem + OFF_BIAS);
    const int r1 = r0 + m_base + g2;
#pragma unroll
    for (int ni = 0; ni < 6; ni++) {
        const int n = nh * 96 + n_base + 8 * ni + i2;
        const float b0 = bias[n], b1 = bias[n + 1];
        const float v00 = acc[ni][0] + b0, v01 = acc[ni][1] + b1;
        const float v10 = acc[ni][2] + b0, v11 = acc[ni][3] + b1;
        if (n < 64) {
            if (r1 < NN)
                *(__nv_bfloat162*)(g_xlb + (size_t)r1 * C + n) =
                    __float22bfloat162_rn(make_float2(v00, v01));
            if (r1 + 8 < NN)
                *(__nv_bfloat162*)(g_xlb + (size_t)(r1 + 8) * C + n) =
                    __float22bfloat162_rn(make_float2(v10, v11));
        } else {
            float* basep;
            int col;
            if (n < 128) { basep = g_xr; col = n - 64; }
            else         { basep = out;  col = n - 128; }
            if (r1 < NN)
                *(float2*)(basep + (size_t)r1 * C + col) = make_float2(v00, v01);
            if (r1 + 8 < NN)
                *(float2*)(basep + (size_t)(r1 + 8) * C + col) = make_float2(v10, v11);
        }
    }
}

// ---------------- CSR build ----------------
__global__ void k_zero() {
    int i = blockIdx.x * 256 + threadIdx.x;
    if (i < NN) g_deg[i] = 0;
}
__global__ void k_hist(const int* __restrict__ ei) {
    int e = blockIdx.x * 256 + threadIdx.x;
    if (e < NEDGE) atomicAdd(&g_deg[ei[NEDGE + e]], 1);
}
__global__ void k_scan1() {
    __shared__ int s[1024];
    const int gid = blockIdx.x * 1024 + threadIdx.x;
    int v = (gid < NN) ? g_deg[gid] : 0;
    s[threadIdx.x] = v;
    __syncthreads();
#pragma unroll
    for (int off = 1; off < 1024; off <<= 1) {
        int t = (threadIdx.x >= off) ? s[threadIdx.x - off] : 0;
        __syncthreads();
        s[threadIdx.x] += t;
        __syncthreads();
    }
    if (gid < NN) g_tmp[gid] = s[threadIdx.x];
    if (threadIdx.x == 1023) g_bsum[blockIdx.x] = s[1023];
}
__global__ void k_scan2() {
    __shared__ int s[128];
    const int t = threadIdx.x;
    int v = (t < NB1) ? g_bsum[t] : 0;
    s[t] = v;
    __syncthreads();
#pragma unroll
    for (int off = 1; off < 128; off <<= 1) {
        int u = (t >= off) ? s[t - off] : 0;
        __syncthreads();
        s[t] += u;
        __syncthreads();
    }
    g_boff[t] = s[t] - v;
}
__global__ void k_scan3() {
    const int i = blockIdx.x * 256 + threadIdx.x;
    if (i < NN) {
        int rp = g_tmp[i] - g_deg[i] + g_boff[i >> 10];
        g_rowptr[i] = rp;
        g_cursor[i] = rp;
    }
    if (i == 0) g_rowptr[NN] = NEDGE;
}
__global__ void k_scatter(const int* __restrict__ ei) {
    int e = blockIdx.x * 256 + threadIdx.x;
    if (e < NEDGE) {
        int src = ei[e];
        int dst = ei[NEDGE + e];
        int pos = atomicAdd(&g_cursor[dst], 1);
        g_csrc[pos] = src;
    }
}

// ---------------- fused edge phase: 8 edges/iter, 4 lanes/edge, bf16 gathers (R14) ----
__global__ void __launch_bounds__(256)
k_fused(const float* __restrict__ att, float* __restrict__ out) {
    const int w = (blockIdx.x * 256 + threadIdx.x) >> 5;
    if (w >= NN) return;
    const int lane = threadIdx.x & 31;
    const int g = lane >> 2;          // edge group 0..7
    const int s = lane & 3;           // channel slot: channels s*16 .. s*16+15
    const int dst = w;

    const float4* att4 = (const float4*)att;
    const float4* xr4 = (const float4*)g_xr;
    const uint4* xlb4 = (const uint4*)g_xlb;   // 8 bf16 per uint4; row = 8 uint4

    float4 a[4], xr[4];
#pragma unroll
    for (int j = 0; j < 4; j++) {
        a[j]  = att4[s * 4 + j];
        xr[j] = xr4[(size_t)dst * 16 + s * 4 + j];
    }

    const int start = g_rowptr[dst];
    const int total = g_rowptr[dst + 1] - start + 1;  // + self loop at virtual idx 0
    const int deg = total - 1;

    const int p0 = (lane < deg)      ? g_csrc[start + lane]      : 0;
    const int p1 = (lane + 32 < deg) ? g_csrc[start + 32 + lane] : 0;

    float4 acc[4];
#pragma unroll
    for (int j = 0; j < 4; j++) acc[j] = make_float4(0.f, 0.f, 0.f, 0.f);
    float d = 0.f;

    for (int base = 0; base < total; base += 8) {
        const int idx = base + g;
        const bool valid = idx < total;
        const int sh0 = __shfl_sync(0xffffffffu, p0, (idx - 1) & 31);
        const int sh1 = __shfl_sync(0xffffffffu, p1, (idx - 33) & 31);
        float4 x[4];
#pragma unroll
        for (int j = 0; j < 4; j++) x[j] = make_float4(0.f, 0.f, 0.f, 0.f);
        float ek = 0.f;
        if (valid) {
            int src;
            if (idx == 0)       src = dst;
            else if (idx <= 32) src = sh0;
            else if (idx <= 64) src = sh1;
            else                src = g_csrc[start + idx - 1];  // ~never taken
            const uint4 u0 = xlb4[(size_t)src * 8 + s * 2];
            const uint4 u1 = xlb4[(size_t)src * 8 + s * 2 + 1];
            const float2 f0 = __bfloat1622float2(*(const __nv_bfloat162*)&u0.x);
            const float2 f1 = __bfloat1622float2(*(const __nv_bfloat162*)&u0.y);
            const float2 f2 = __bfloat1622float2(*(const __nv_bfloat162*)&u0.z);
            const float2 f3 = __bfloat1622float2(*(const __nv_bfloat162*)&u0.w);
            const float2 f4 = __bfloat1622float2(*(const __nv_bfloat162*)&u1.x);
            const float2 f5 = __bfloat1622float2(*(const __nv_bfloat162*)&u1.y);
            const float2 f6 = __bfloat1622float2(*(const __nv_bfloat162*)&u1.z);
            const float2 f7 = __bfloat1622float2(*(const __nv_bfloat162*)&u1.w);
            x[0] = make_float4(f0.x, f0.y, f1.x, f1.y);
            x[1] = make_float4(f2.x, f2.y, f3.x, f3.y);
            x[2] = make_float4(f4.x, f4.y, f5.x, f5.y);
            x[3] = make_float4(f6.x, f6.y, f7.x, f7.y);
#pragma unroll
            for (int j = 0; j < 4; j++) {
                float t;
                t = x[j].x + xr[j].x; ek += a[j].x * fmaxf(t, 0.2f * t);
                t = x[j].y + xr[j].y; ek += a[j].y * fmaxf(t, 0.2f * t);
                t = x[j].z + xr[j].z; ek += a[j].z * fmaxf(t, 0.2f * t);
                t = x[j].w + xr[j].w; ek += a[j].w * fmaxf(t, 0.2f * t);
            }
        }
        ek += __shfl_xor_sync(0xffffffffu, ek, 1);
        ek += __shfl_xor_sync(0xffffffffu, ek, 2);
        const float p = valid ? __expf(ek) : 0.f;
        d += p;
#pragma unroll
        for (int j = 0; j < 4; j++) {
            acc[j].x += p * x[j].x; acc[j].y += p * x[j].y;
            acc[j].z += p * x[j].z; acc[j].w += p * x[j].w;
        }
    }

#pragma unroll
    for (int o = 4; o <= 16; o <<= 1) {
        d += __shfl_xor_sync(0xffffffffu, d, o);
#pragma unroll
        for (int j = 0; j < 4; j++) {
            acc[j].x += __shfl_xor_sync(0xffffffffu, acc[j].x, o);
            acc[j].y += __shfl_xor_sync(0xffffffffu, acc[j].y, o);
            acc[j].z += __shfl_xor_sync(0xffffffffu, acc[j].z, o);
            acc[j].w += __shfl_xor_sync(0xffffffffu, acc[j].w, o);
        }
    }

    if (g == 0) {
        const float inv = 1.0f / d;
        float4* o4 = (float4*)out + (size_t)dst * 16 + s * 4;
#pragma unroll
        for (int j = 0; j < 4; j++) {
            float4 l = o4[j];
            l.x = fmaxf(l.x + acc[j].x * inv, 0.f);
            l.y = fmaxf(l.y + acc[j].y * inv, 0.f);
            l.z = fmaxf(l.z + acc[j].z * inv, 0.f);
            l.w = fmaxf(l.w + acc[j].w * inv, 0.f);
            o4[j] = l;
        }
    }
}

// ---------------- launch: GEMM (stream 0) overlapped with CSR build (s2) ----------------
extern "C" void kernel_launch(void* const* d_in, const int* in_sizes, int n_in,
                              void* d_out, int out_size) {
    const float* node = (const float*)d_in[0];
    const int*   ei   = (const int*)d_in[1];   // int32 on device
    const float* Wl   = (const float*)d_in[2];
    const float* bl   = (const float*)d_in[3];
    const float* Wr   = (const float*)d_in[4];
    const float* br   = (const float*)d_in[5];
    const float* att  = (const float*)d_in[6];
    const float* gb   = (const float*)d_in[7];
    const float* Wn   = (const float*)d_in[8];
    const float* bn   = (const float*)d_in[9];
    float* out = (float*)d_out;

    static cudaStream_t s2 = nullptr;
    static cudaEvent_t ev_fork = nullptr, ev_join = nullptr;
    if (!s2) {  // first call happens outside graph capture
        cudaStreamCreateWithFlags(&s2, cudaStreamNonBlocking);
        cudaEventCreateWithFlags(&ev_fork, cudaEventDisableTiming);
        cudaEventCreateWithFlags(&ev_join, cudaEventDisableTiming);
        cudaFuncSetAttribute(k_gemm_mma, cudaFuncAttributeMaxDynamicSharedMemorySize, SMEM_TOT);
    }

    cudaEventRecord(ev_fork, 0);
    cudaStreamWaitEvent(s2, ev_fork, 0);
    k_zero<<<(NN + 255) / 256, 256, 0, s2>>>();              // launch 1
    k_hist<<<(NEDGE + 255) / 256, 256, 0, s2>>>(ei);         // launch 2
    k_wprep<<<(768 * NOUT + 255) / 256, 256>>>(Wl, Wr, Wn);  // launch 3
    k_gemm_mma<<<2 * ((NN + 63) / 64), 256, SMEM_TOT>>>(node, bl, br, bn, gb, out);  // launch 4 (profiled)
    k_scan1<<<NB1, 1024, 0, s2>>>();
    k_scan2<<<1, 128, 0, s2>>>();
    k_scan3<<<(NN + 255) / 256, 256, 0, s2>>>();
    k_scatter<<<(NEDGE + 255) / 256, 256, 0, s2>>>(ei);
    cudaEventRecord(ev_join, s2);

    cudaStreamWaitEvent(0, ev_join, 0);
    k_fused<<<(NN * 32 + 255) / 256, 256>>>(att, out);
}

// round 17
// speedup vs baseline: 1.1075x; 1.0737x over previous
#include <cuda_runtime.h>
#include <cuda_bf16.h>
#include <cstdint>

#define NN 100000
#define NEDGE 3200000
#define CIN 768
#define C 64
#define NOUT 192
#define NB1 98  /* ceil(100000/1024) */

// ---------------- static device scratch ----------------
__device__ __align__(16) __nv_bfloat16 g_xlb[(size_t)NN * C];  // bf16 x_l for edge phase
__device__ float g_xr[(size_t)NN * C];
__device__ __align__(16) __nv_bfloat16 g_bhi[768 * NOUT];  // [k][n], rows of 384B
__device__ __align__(16) __nv_bfloat16 g_blo[768 * NOUT];
__device__ int   g_deg[NN];
__device__ int   g_tmp[NN];
__device__ int   g_bsum[128];
__device__ int   g_boff[128];
__device__ int   g_rowptr[NN + 1];
__device__ int   g_cursor[NN];
__device__ int   g_csrc[NEDGE];

// ---------------- smem layout (bytes): A double-buffered, B half-stage ring ----
#define SA_STRIDE 144          /* 72 bf16 per row (64 + 8 pad) */
#define SB_STRIDE 400          /* 200 bf16 per row (192 + 8 pad) */
#define OFF_A0H  0             /* 64 x 144 = 9216 */
#define OFF_A0L  9216
#define OFF_A1H  18432
#define OFF_A1L  27648
#define OFF_BH   36864         /* 64 x 400 = 25600 (2 stages of 32 rows) */
#define OFF_BL   62464
#define OFF_BIAS 88064         /* 192 floats */
#define SMEM_TOT 88832

__device__ __forceinline__ uint32_t smem_u32(const void* p) {
    uint32_t a;
    asm("{ .reg .u64 t; cvta.to.shared.u64 t, %1; cvt.u32.u64 %0, t; }"
        : "=r"(a) : "l"(p));
    return a;
}
__device__ __forceinline__ void cpa16(uint32_t dst, const void* src) {
    asm volatile("cp.async.cg.shared.global [%0], [%1], 16;"
                 :: "r"(dst), "l"(src) : "memory");
}
#define CPA_COMMIT() asm volatile("cp.async.commit_group;" ::: "memory")
#define CPA_WAIT1()  asm volatile("cp.async.wait_group 1;" ::: "memory")
__device__ __forceinline__ void ldsm4(uint32_t* r, uint32_t addr) {
    asm volatile("ldmatrix.sync.aligned.m8n8.x4.shared.b16 {%0,%1,%2,%3}, [%4];"
                 : "=r"(r[0]), "=r"(r[1]), "=r"(r[2]), "=r"(r[3]) : "r"(addr));
}
__device__ __forceinline__ void ldsm4t(uint32_t* r, uint32_t addr) {
    asm volatile("ldmatrix.sync.aligned.m8n8.x4.trans.shared.b16 {%0,%1,%2,%3}, [%4];"
                 : "=r"(r[0]), "=r"(r[1]), "=r"(r[2]), "=r"(r[3]) : "r"(addr));
}
__device__ __forceinline__ void mma16816(float* d, const uint32_t* a,
                                         uint32_t b0, uint32_t b1) {
    asm volatile(
        "mma.sync.aligned.m16n8k16.row.col.f32.bf16.bf16.f32 "
        "{%0,%1,%2,%3}, {%4,%5,%6,%7}, {%8,%9}, {%0,%1,%2,%3};"
        : "+f"(d[0]), "+f"(d[1]), "+f"(d[2]), "+f"(d[3])
        : "r"(a[0]), "r"(a[1]), "r"(a[2]), "r"(a[3]), "r"(b0), "r"(b1));
}

// ---------------- W prep: split into bf16 hi/lo, [k][n] layout ----------------
__global__ void k_wprep(const float* __restrict__ Wl, const float* __restrict__ Wr,
                        const float* __restrict__ Wn) {
    const int i = blockIdx.x * 256 + threadIdx.x;
    if (i >= 768 * NOUT) return;
    const int k = i / NOUT, n = i % NOUT;
    const float* W = n < 64 ? Wl : n < 128 ? Wr : Wn;
    const float w = W[k * 64 + (n & 63)];
    const __nv_bfloat16 h = __float2bfloat16(w);
    g_bhi[i] = h;
    g_blo[i] = __float2bfloat16(w - __bfloat162float(h));
}

// ---------------- tensor-core triple GEMM: 64x192 tile, pipelined (FROZEN, R10) ----
__global__ void __launch_bounds__(256, 2)
k_gemm_mma(const float* __restrict__ node,
           const float* __restrict__ bl, const float* __restrict__ br,
           const float* __restrict__ bn, const float* __restrict__ gb,
           float* __restrict__ out) {
    extern __shared__ char smem[];
    const uint32_t sb = smem_u32(smem);
    const int tid = threadIdx.x;
    const int warp = tid >> 5, lane = tid & 31;
    const int r0 = blockIdx.x * 64;

    if (tid < NOUT) {
        const float b = tid < 64 ? bl[tid]
                      : tid < 128 ? br[tid - 64]
                      : bn[tid - 128] + gb[tid - 128];
        *(float*)(smem + OFF_BIAS + tid * 4) = b;
    }

    float acc[2][6][4];
#pragma unroll
    for (int mi = 0; mi < 2; mi++)
#pragma unroll
        for (int ni = 0; ni < 6; ni++)
#pragma unroll
            for (int j = 0; j < 4; j++) acc[mi][ni][j] = 0.f;

    const int wm = warp & 1, wn = warp >> 1;   // 2 x 4 warp grid
    const int m_base = wm * 32;                // warp tile 32 x 48
    const int n_base = wn * 48;
    const int a_row = lane & 15;
    const int a_koff = (lane >> 4) << 3;
    const int b_row = lane & 15;
    const int b_noff = (lane >> 4) << 3;

    const int ar = tid >> 4;            // A-load base row (0..15)
    const int ac4 = tid & 15;           // float4 column

    auto fill_stage = [&](int s, int kcn) {
#pragma unroll
        for (int i = 0; i < 3; i++) {
            const int q = tid + i * 256;          // 0..767
            const int rr = q / 24, f = q % 24;
            const uint32_t off = (uint32_t)((s * 32 + rr) * SB_STRIDE + f * 16);
            const size_t srow = (size_t)(kcn * 64 + s * 32 + rr) * 384 + f * 16;
            cpa16(sb + OFF_BH + off, (const char*)g_bhi + srow);
            cpa16(sb + OFF_BL + off, (const char*)g_blo + srow);
        }
    };
    float4 areg[4];
    auto lda = [&](int kcn) {
#pragma unroll
        for (int i = 0; i < 4; i++) {
            const int r = ar + i * 16;
            areg[i] = (r0 + r < NN)
                ? *(const float4*)(node + (size_t)(r0 + r) * CIN + kcn * 64 + ac4 * 4)
                : make_float4(0.f, 0.f, 0.f, 0.f);
        }
    };
    auto cvta = [&](int p) {
        const int offh = p ? OFF_A1H : OFF_A0H;
        const int offl = p ? OFF_A1L : OFF_A0L;
#pragma unroll
        for (int i = 0; i < 4; i++) {
            const int r = ar + i * 16;
            const float4 v = areg[i];
            const __nv_bfloat16 h0 = __float2bfloat16(v.x), h1 = __float2bfloat16(v.y);
            const __nv_bfloat16 h2 = __float2bfloat16(v.z), h3 = __float2bfloat16(v.w);
            __nv_bfloat162* ph = (__nv_bfloat162*)(smem + offh + r * SA_STRIDE + ac4 * 8);
            ph[0] = __nv_bfloat162(h0, h1);
            ph[1] = __nv_bfloat162(h2, h3);
            const __nv_bfloat16 l0 = __float2bfloat16(v.x - __bfloat162float(h0));
            const __nv_bfloat16 l1 = __float2bfloat16(v.y - __bfloat162float(h1));
            const __nv_bfloat16 l2 = __float2bfloat16(v.z - __bfloat162float(h2));
            const __nv_bfloat16 l3 = __float2bfloat16(v.w - __bfloat162float(h3));
            __nv_bfloat162* pl = (__nv_bfloat162*)(smem + offl + r * SA_STRIDE + ac4 * 8);
            pl[0] = __nv_bfloat162(l0, l1);
            pl[1] = __nv_bfloat162(l2, l3);
        }
    };
    auto mma_half = [&](int half, int p) {
        const int offh = p ? OFF_A1H : OFF_A0H;
        const int offl = p ? OFF_A1L : OFF_A0L;
#pragma unroll
        for (int ks = half * 2; ks < half * 2 + 2; ks++) {
            const int k0 = ks * 16;
            uint32_t ah[2][4], al[2][4];
#pragma unroll
            for (int mi = 0; mi < 2; mi++) {
                const uint32_t aoff =
                    (uint32_t)((m_base + 16 * mi + a_row) * SA_STRIDE + (k0 + a_koff) * 2);
                ldsm4(ah[mi], sb + offh + aoff);
                ldsm4(al[mi], sb + offl + aoff);
            }
#pragma unroll
            for (int np = 0; np < 3; np++) {
                const int n0 = n_base + np * 16;
                const uint32_t boff =
                    (uint32_t)((k0 + b_row) * SB_STRIDE + (n0 + b_noff) * 2);
                uint32_t bh[4];
                ldsm4t(bh, sb + OFF_BH + boff);
#pragma unroll
                for (int mi = 0; mi < 2; mi++) {
                    mma16816(acc[mi][2 * np],     ah[mi], bh[0], bh[1]);
                    mma16816(acc[mi][2 * np + 1], ah[mi], bh[2], bh[3]);
                    mma16816(acc[mi][2 * np],     al[mi], bh[0], bh[1]);
                    mma16816(acc[mi][2 * np + 1], al[mi], bh[2], bh[3]);
                }
                uint32_t bo[4];
                ldsm4t(bo, sb + OFF_BL + boff);
#pragma unroll
                for (int mi = 0; mi < 2; mi++) {
                    mma16816(acc[mi][2 * np],     ah[mi], bo[0], bo[1]);
                    mma16816(acc[mi][2 * np + 1], ah[mi], bo[2], bo[3]);
                }
            }
        }
    };

    lda(0);
    fill_stage(0, 0); CPA_COMMIT();
    fill_stage(1, 0); CPA_COMMIT();
    cvta(0);
    int p = 0;

    for (int kc = 0; kc < 12; kc++) {
        const int kcn = (kc < 11) ? kc + 1 : 11;
        CPA_WAIT1(); __syncthreads();
        lda(kcn);
        mma_half(0, p);
        __syncthreads();
        fill_stage(0, kcn); CPA_COMMIT();
        CPA_WAIT1(); __syncthreads();
        mma_half(1, p);
        cvta(p ^ 1);
        __syncthreads();
        fill_stage(1, kcn); CPA_COMMIT();
        p ^= 1;
    }

    // epilogue: x_l -> bf16 g_xlb; x_r -> fp32 g_xr; lin -> out
    const int g2 = lane >> 2;
    const int i2 = (lane & 3) << 1;
    const float* bias = (const float*)(smem + OFF_BIAS);
#pragma unroll
    for (int mi = 0; mi < 2; mi++) {
        const int r1 = r0 + m_base + 16 * mi + g2;
#pragma unroll
        for (int ni = 0; ni < 6; ni++) {
            const int n = n_base + 8 * ni + i2;
            const float b0 = bias[n], b1 = bias[n + 1];
            const float v00 = acc[mi][ni][0] + b0, v01 = acc[mi][ni][1] + b1;
            const float v10 = acc[mi][ni][2] + b0, v11 = acc[mi][ni][3] + b1;
            if (n < 64) {
                if (r1 < NN)
                    *(__nv_bfloat162*)(g_xlb + (size_t)r1 * C + n) =
                        __float22bfloat162_rn(make_float2(v00, v01));
                if (r1 + 8 < NN)
                    *(__nv_bfloat162*)(g_xlb + (size_t)(r1 + 8) * C + n) =
                        __float22bfloat162_rn(make_float2(v10, v11));
            } else {
                float* basep;
                int col;
                if (n < 128) { basep = g_xr; col = n - 64; }
                else         { basep = out;  col = n - 128; }
                if (r1 < NN)
                    *(float2*)(basep + (size_t)r1 * C + col) = make_float2(v00, v01);
                if (r1 + 8 < NN)
                    *(float2*)(basep + (size_t)(r1 + 8) * C + col) = make_float2(v10, v11);
            }
        }
    }
}

// ---------------- CSR build ----------------
__global__ void k_zero() {
    int i = blockIdx.x * 256 + threadIdx.x;
    if (i < NN) g_deg[i] = 0;
}
__global__ void k_hist(const int* __restrict__ ei) {
    int e = blockIdx.x * 256 + threadIdx.x;
    if (e < NEDGE) atomicAdd(&g_deg[ei[NEDGE + e]], 1);
}
__global__ void k_scan1() {
    __shared__ int s[1024];
    const int gid = blockIdx.x * 1024 + threadIdx.x;
    int v = (gid < NN) ? g_deg[gid] : 0;
    s[threadIdx.x] = v;
    __syncthreads();
#pragma unroll
    for (int off = 1; off < 1024; off <<= 1) {
        int t = (threadIdx.x >= off) ? s[threadIdx.x - off] : 0;
        __syncthreads();
        s[threadIdx.x] += t;
        __syncthreads();
    }
    if (gid < NN) g_tmp[gid] = s[threadIdx.x];
    if (threadIdx.x == 1023) g_bsum[blockIdx.x] = s[1023];
}
__global__ void k_scan2() {
    __shared__ int s[128];
    const int t = threadIdx.x;
    int v = (t < NB1) ? g_bsum[t] : 0;
    s[t] = v;
    __syncthreads();
#pragma unroll
    for (int off = 1; off < 128; off <<= 1) {
        int u = (t >= off) ? s[t - off] : 0;
        __syncthreads();
        s[t] += u;
        __syncthreads();
    }
    g_boff[t] = s[t] - v;
}
__global__ void k_scan3() {
    const int i = blockIdx.x * 256 + threadIdx.x;
    if (i < NN) {
        int rp = g_tmp[i] - g_deg[i] + g_boff[i >> 10];
        g_rowptr[i] = rp;
        g_cursor[i] = rp;
    }
    if (i == 0) g_rowptr[NN] = NEDGE;
}
__global__ void k_scatter(const int* __restrict__ ei) {
    int e = blockIdx.x * 256 + threadIdx.x;
    if (e < NEDGE) {
        int src = ei[e];
        int dst = ei[NEDGE + e];
        int pos = atomicAdd(&g_cursor[dst], 1);
        g_csrc[pos] = src;
    }
}

// ---------------- fused edge phase: R14 structure + sector-packed gather indices ----
// Lane s loads uint4 idx {s, 4+s}: each gather LDG's 4-lane group covers 64
// contiguous bytes (full 32B sectors). Lane s owns channels [8s,8s+8) and
// [32+8s,32+8s+8); att/xr/out indices permuted to match. Register-neutral.
__global__ void __launch_bounds__(256)
k_fused(const float* __restrict__ att, float* __restrict__ out) {
    const int w = (blockIdx.x * 256 + threadIdx.x) >> 5;
    if (w >= NN) return;
    const int lane = threadIdx.x & 31;
    const int g = lane >> 2;          // edge group 0..7
    const int s = lane & 3;
    const int dst = w;

    const float4* att4 = (const float4*)att;
    const float4* xr4 = (const float4*)g_xr;
    const uint4* xlb4 = (const uint4*)g_xlb;   // 8 bf16 per uint4; row = 8 uint4

    // channels: x[0],x[1] = 8s..8s+7 (float4 idx 2s, 2s+1)
    //           x[2],x[3] = 32+8s..32+8s+7 (float4 idx 8+2s, 8+2s+1)
    float4 a[4], xr[4];
    a[0]  = att4[2 * s];      a[1] = att4[2 * s + 1];
    a[2]  = att4[8 + 2 * s];  a[3] = att4[8 + 2 * s + 1];
    xr[0] = xr4[(size_t)dst * 16 + 2 * s];
    xr[1] = xr4[(size_t)dst * 16 + 2 * s + 1];
    xr[2] = xr4[(size_t)dst * 16 + 8 + 2 * s];
    xr[3] = xr4[(size_t)dst * 16 + 8 + 2 * s + 1];

    const int start = g_rowptr[dst];
    const int total = g_rowptr[dst + 1] - start + 1;  // + self loop at virtual idx 0
    const int deg = total - 1;

    // preload up to 64 neighbor srcs (2 per lane)
    const int p0 = (lane < deg)      ? g_csrc[start + lane]      : 0;
    const int p1 = (lane + 32 < deg) ? g_csrc[start + 32 + lane] : 0;

    float4 acc[4];
#pragma unroll
    for (int j = 0; j < 4; j++) acc[j] = make_float4(0.f, 0.f, 0.f, 0.f);
    float d = 0.f;

    for (int base = 0; base < total; base += 8) {
        const int idx = base + g;
        const bool valid = idx < total;
        const int sh0 = __shfl_sync(0xffffffffu, p0, (idx - 1) & 31);
        const int sh1 = __shfl_sync(0xffffffffu, p1, (idx - 33) & 31);
        float4 x[4];
#pragma unroll
        for (int j = 0; j < 4; j++) x[j] = make_float4(0.f, 0.f, 0.f, 0.f);
        float ek = 0.f;
        if (valid) {
            int src;
            if (idx == 0)       src = dst;
            else if (idx <= 32) src = sh0;
            else if (idx <= 64) src = sh1;
            else                src = g_csrc[start + idx - 1];  // ~never taken
            // 2 x LDG.128 of bf16; 4-lane group covers 64B contiguous per LDG
            const uint4 u0 = xlb4[(size_t)src * 8 + s];
            const uint4 u1 = xlb4[(size_t)src * 8 + 4 + s];
            const float2 f0 = __bfloat1622float2(*(const __nv_bfloat162*)&u0.x);
            const float2 f1 = __bfloat1622float2(*(const __nv_bfloat162*)&u0.y);
            const float2 f2 = __bfloat1622float2(*(const __nv_bfloat162*)&u0.z);
            const float2 f3 = __bfloat1622float2(*(const __nv_bfloat162*)&u0.w);
            const float2 f4 = __bfloat1622float2(*(const __nv_bfloat162*)&u1.x);
            const float2 f5 = __bfloat1622float2(*(const __nv_bfloat162*)&u1.y);
            const float2 f6 = __bfloat1622float2(*(const __nv_bfloat162*)&u1.z);
            const float2 f7 = __bfloat1622float2(*(const __nv_bfloat162*)&u1.w);
            x[0] = make_float4(f0.x, f0.y, f1.x, f1.y);
            x[1] = make_float4(f2.x, f2.y, f3.x, f3.y);
            x[2] = make_float4(f4.x, f4.y, f5.x, f5.y);
            x[3] = make_float4(f6.x, f6.y, f7.x, f7.y);
#pragma unroll
            for (int j = 0; j < 4; j++) {
                float t;
                t = x[j].x + xr[j].x; ek += a[j].x * fmaxf(t, 0.2f * t);
                t = x[j].y + xr[j].y; ek += a[j].y * fmaxf(t, 0.2f * t);
                t = x[j].z + xr[j].z; ek += a[j].z * fmaxf(t, 0.2f * t);
                t = x[j].w + xr[j].w; ek += a[j].w * fmaxf(t, 0.2f * t);
            }
        }
        ek += __shfl_xor_sync(0xffffffffu, ek, 1);
        ek += __shfl_xor_sync(0xffffffffu, ek, 2);
        const float p = valid ? __expf(ek) : 0.f;
        d += p;
#pragma unroll
        for (int j = 0; j < 4; j++) {
            acc[j].x += p * x[j].x; acc[j].y += p * x[j].y;
            acc[j].z += p * x[j].z; acc[j].w += p * x[j].w;
        }
    }

    // cross-group reduction (groups differ in lane bits 2-4)
#pragma unroll
    for (int o = 4; o <= 16; o <<= 1) {
        d += __shfl_xor_sync(0xffffffffu, d, o);
#pragma unroll
        for (int j = 0; j < 4; j++) {
            acc[j].x += __shfl_xor_sync(0xffffffffu, acc[j].x, o);
            acc[j].y += __shfl_xor_sync(0xffffffffu, acc[j].y, o);
            acc[j].z += __shfl_xor_sync(0xffffffffu, acc[j].z, o);
            acc[j].w += __shfl_xor_sync(0xffffffffu, acc[j].w, o);
        }
    }

    if (g == 0) {
        const float inv = 1.0f / d;
        float4* o4 = (float4*)out + (size_t)dst * 16;
        const int oi[4] = {2 * s, 2 * s + 1, 8 + 2 * s, 8 + 2 * s + 1};
#pragma unroll
        for (int j = 0; j < 4; j++) {
            float4 l = o4[oi[j]];
            l.x = fmaxf(l.x + acc[j].x * inv, 0.f);
            l.y = fmaxf(l.y + acc[j].y * inv, 0.f);
            l.z = fmaxf(l.z + acc[j].z * inv, 0.f);
            l.w = fmaxf(l.w + acc[j].w * inv, 0.f);
            o4[oi[j]] = l;
        }
    }
}

// ---------------- launch: GEMM (stream 0) overlapped with CSR build (s2) ----------------
extern "C" void kernel_launch(void* const* d_in, const int* in_sizes, int n_in,
                              void* d_out, int out_size) {
    const float* node = (const float*)d_in[0];
    const int*   ei   = (const int*)d_in[1];   // int32 on device
    const float* Wl   = (const float*)d_in[2];
    const float* bl   = (const float*)d_in[3];
    const float* Wr   = (const float*)d_in[4];
    const float* br   = (const float*)d_in[5];
    const float* att  = (const float*)d_in[6];
    const float* gb   = (const float*)d_in[7];
    const float* Wn   = (const float*)d_in[8];
    const float* bn   = (const float*)d_in[9];
    float* out = (float*)d_out;

    static cudaStream_t s2 = nullptr;
    static cudaEvent_t ev_fork = nullptr, ev_join = nullptr;
    if (!s2) {  // first call happens outside graph capture
        cudaStreamCreateWithFlags(&s2, cudaStreamNonBlocking);
        cudaEventCreateWithFlags(&ev_fork, cudaEventDisableTiming);
        cudaEventCreateWithFlags(&ev_join, cudaEventDisableTiming);
        cudaFuncSetAttribute(k_gemm_mma, cudaFuncAttributeMaxDynamicSharedMemorySize, SMEM_TOT);
    }

    cudaEventRecord(ev_fork, 0);
    cudaStreamWaitEvent(s2, ev_fork, 0);
    k_zero<<<(NN + 255) / 256, 256, 0, s2>>>();              // launch 1
    k_hist<<<(NEDGE + 255) / 256, 256, 0, s2>>>(ei);         // launch 2
    k_wprep<<<(768 * NOUT + 255) / 256, 256>>>(Wl, Wr, Wn);  // launch 3
    k_gemm_mma<<<(NN + 63) / 64, 256, SMEM_TOT>>>(node, bl, br, bn, gb, out);  // launch 4 (profiled)
    k_scan1<<<NB1, 1024, 0, s2>>>();
    k_scan2<<<1, 128, 0, s2>>>();
    k_scan3<<<(NN + 255) / 256, 256, 0, s2>>>();
    k_scatter<<<(NEDGE + 255) / 256, 256, 0, s2>>>(ei);
    cudaEventRecord(ev_join, s2);

    cudaStreamWaitEvent(0, ev_join, 0);
    k_fused<<<(NN * 32 + 255) / 256, 256>>>(att, out);
}